// round 17
// baseline (speedup 1.0000x reference)
#include <cuda_runtime.h>
#include <cuda_bf16.h>
#include <cuda_fp16.h>
#include <math_constants.h>
#include <cstdint>

// Problem constants: B=16, N=1024, M=512, D=512
#define B_ 16
#define N_ 1024
#define M_ 512
#define D_ 512

// ---------------------------------------------------------------------------
// Scratch (device globals; no allocation allowed)
// ---------------------------------------------------------------------------
__device__ float g_sim[B_ * N_ * M_];                 // similarity fp32 (32 MB)
__device__ float g_S2 [B_ * N_ * M_];                 // S2 fp32 (32 MB)
__device__ float g_X  [B_ * M_ * D_];                 // X = S2^T @ C fp32 (16 MB)
__device__ float g_cw [B_ * N_];
__device__ float g_qw [B_ * M_];
// G1 path (3-term bf16, accuracy-critical: feeds softmax logits)
__device__ __nv_bfloat16 g_CWh[B_ * N_ * D_];         // (C*w4mlu) hi/lo
__device__ __nv_bfloat16 g_CWl[B_ * N_ * D_];
__device__ __nv_bfloat16 g_Qbh[B_ * M_ * D_];         // Q hi/lo bf16 [m][d]
__device__ __nv_bfloat16 g_Qbl[B_ * M_ * D_];
// 1-term fp16 path
__device__ __half g_S1 [B_ * N_ * M_];                // S1 fp16 [n][m]
__device__ __half g_Qt [B_ * D_ * M_];                // Q^T fp16 [d][m]
__device__ __half g_Ct [B_ * D_ * N_];                // C^T fp16 [d][n]
__device__ __half g_S2t[B_ * M_ * N_];                // S2^T fp16 [m][n]
__device__ __half g_Xt [B_ * D_ * M_];                // X^T fp16 [d][m]

// ---------------------------------------------------------------------------
// Helpers
// ---------------------------------------------------------------------------
__device__ __forceinline__ uint32_t smem_u32(const void* p) {
    uint32_t a;
    asm("{ .reg .u64 tmp; cvta.to.shared.u64 tmp, %1; cvt.u32.u64 %0, tmp; }"
        : "=r"(a) : "l"(p));
    return a;
}

__device__ __forceinline__ void cp16(void* dst, const void* src) {
    uint32_t d = smem_u32(dst);
    asm volatile("cp.async.ca.shared.global [%0], [%1], 16;"
                 :: "r"(d), "l"(src) : "memory");
}
#define CP_COMMIT() asm volatile("cp.async.commit_group;" ::: "memory")
#define CP_WAIT1()  asm volatile("cp.async.wait_group 1;" ::: "memory")
#define CP_WAIT0()  asm volatile("cp.async.wait_group 0;" ::: "memory")

__device__ __forceinline__ void mma_bf16(float* d, const unsigned* a, const unsigned* b) {
    asm volatile(
        "mma.sync.aligned.m16n8k16.row.col.f32.bf16.bf16.f32 "
        "{%0,%1,%2,%3}, {%4,%5,%6,%7}, {%8,%9}, {%0,%1,%2,%3};"
        : "+f"(d[0]), "+f"(d[1]), "+f"(d[2]), "+f"(d[3])
        : "r"(a[0]), "r"(a[1]), "r"(a[2]), "r"(a[3]), "r"(b[0]), "r"(b[1]));
}
__device__ __forceinline__ void mma_f16(float* d, const unsigned* a, const unsigned* b) {
    asm volatile(
        "mma.sync.aligned.m16n8k16.row.col.f32.f16.f16.f32 "
        "{%0,%1,%2,%3}, {%4,%5,%6,%7}, {%8,%9}, {%0,%1,%2,%3};"
        : "+f"(d[0]), "+f"(d[1]), "+f"(d[2]), "+f"(d[3])
        : "r"(a[0]), "r"(a[1]), "r"(a[2]), "r"(a[3]), "r"(b[0]), "r"(b[1]));
}

// bf16 hi/lo split of a pair of floats
__device__ __forceinline__ __nv_bfloat162 split2(float f0, float f1, __nv_bfloat162& lo) {
    __nv_bfloat162 hi = __floats2bfloat162_rn(f0, f1);
    lo = __floats2bfloat162_rn(f0 - __low2float(hi), f1 - __high2float(hi));
    return hi;
}
__device__ __forceinline__ unsigned bf2u(__nv_bfloat162 v) {
    return *reinterpret_cast<unsigned*>(&v);
}
__device__ __forceinline__ unsigned h2u(__half2 v) {
    return *reinterpret_cast<unsigned*>(&v);
}

// ---------------------------------------------------------------------------
// Row-dot: out[row] = sum_d X[row,d] * w[d]
// ---------------------------------------------------------------------------
__global__ __launch_bounds__(256)
void rowdot_kernel(const float* __restrict__ X, const float* __restrict__ w,
                   float* __restrict__ out, int rows)
{
    int warp = (blockIdx.x * blockDim.x + threadIdx.x) >> 5;
    int lane = threadIdx.x & 31;
    if (warp >= rows) return;
    const float4* x4 = (const float4*)(X + (long)warp * D_);
    const float4* w4 = (const float4*)w;
    float s = 0.f;
    #pragma unroll
    for (int i = 0; i < 4; ++i) {
        float4 a = x4[lane + 32 * i];
        float4 b = w4[lane + 32 * i];
        s += a.x * b.x + a.y * b.y + a.z * b.z + a.w * b.w;
    }
    #pragma unroll
    for (int o = 16; o; o >>= 1) s += __shfl_xor_sync(0xffffffffu, s, o);
    if (lane == 0) out[warp] = s;
}

// ---------------------------------------------------------------------------
// Elementwise split fp32 -> bf16 hi/lo (optional per-d scale by ws)
// ---------------------------------------------------------------------------
template<bool SC>
__global__ __launch_bounds__(256)
void split_kernel(const float* __restrict__ X, const float* __restrict__ ws,
                  __nv_bfloat16* __restrict__ H, __nv_bfloat16* __restrict__ L, int n4)
{
    int i = blockIdx.x * blockDim.x + threadIdx.x;
    if (i >= n4) return;
    float4 v = ((const float4*)X)[i];
    if (SC) {
        int d = (i * 4) & (D_ - 1);
        float4 w = *(const float4*)(ws + d);
        v.x *= w.x; v.y *= w.y; v.z *= w.z; v.w *= w.w;
    }
    __nv_bfloat162 l0, l1;
    __nv_bfloat162 h0 = split2(v.x, v.y, l0);
    __nv_bfloat162 h1 = split2(v.z, v.w, l1);
    ((uint2*)H)[i] = make_uint2(bf2u(h0), bf2u(h1));
    ((uint2*)L)[i] = make_uint2(bf2u(l0), bf2u(l1));
}

// ---------------------------------------------------------------------------
// Transpose to single fp16: X[b][R][Cc] fp32 -> T[b][Cc][R] fp16
// ---------------------------------------------------------------------------
__global__ __launch_bounds__(256)
void transpose_half_kernel(const float* __restrict__ X, int R, int Cc,
                           __half* __restrict__ T)
{
    __shared__ float tile[32][33];
    int b = blockIdx.z;
    const float* Xb = X + (long)b * R * Cc;
    __half* Tb = T + (long)b * R * Cc;
    int rb = blockIdx.y * 32, cb = blockIdx.x * 32;
    int tx = threadIdx.x & 31, ty = threadIdx.x >> 5;   // 32 x 8
    #pragma unroll
    for (int i = 0; i < 4; ++i)
        tile[ty + 8 * i][tx] = Xb[(long)(rb + ty + 8 * i) * Cc + cb + tx];
    __syncthreads();
    #pragma unroll
    for (int i = 0; i < 4; ++i) {
        float v = tile[tx][ty + 8 * i];
        long oi = (long)(cb + ty + 8 * i) * R + rb + tx;
        Tb[oi] = __float2half_rn(v);
    }
}

// ---------------------------------------------------------------------------
// Dual softmax over M=512 per row; writes fp16 S1 and fp32 S2.
// ---------------------------------------------------------------------------
__global__ __launch_bounds__(128)
void softmax2_kernel(const float* __restrict__ Qmask, const float* __restrict__ Cmask)
{
    int row = blockIdx.x;            // b*N + n
    int b   = row >> 10;
    int t   = threadIdx.x;
    int w   = t >> 5, lane = t & 31;

    float4 v  = ((const float4*)(g_sim + (long)row * M_))[t];
    float4 qm = ((const float4*)(Qmask + (long)b * M_))[t];
    float xv[4] = {v.x, v.y, v.z, v.w};
    float qv[4] = {qm.x, qm.y, qm.z, qm.w};

    float m1 = -CUDART_INF_F, m2 = -CUDART_INF_F;
    #pragma unroll
    for (int j = 0; j < 4; ++j) {
        m2 = fmaxf(m2, xv[j]);
        if (qv[j] != 0.f) m1 = fmaxf(m1, xv[j]);
    }
    #pragma unroll
    for (int o = 16; o; o >>= 1) {
        m1 = fmaxf(m1, __shfl_xor_sync(0xffffffffu, m1, o));
        m2 = fmaxf(m2, __shfl_xor_sync(0xffffffffu, m2, o));
    }
    __shared__ float sh1[4], sh2[4];
    if (lane == 0) { sh1[w] = m1; sh2[w] = m2; }
    __syncthreads();
    m1 = fmaxf(fmaxf(sh1[0], sh1[1]), fmaxf(sh1[2], sh1[3]));
    m2 = fmaxf(fmaxf(sh2[0], sh2[1]), fmaxf(sh2[2], sh2[3]));

    float e1[4], e2[4], s1 = 0.f, s2 = 0.f;
    #pragma unroll
    for (int j = 0; j < 4; ++j) {
        e2[j] = __expf(xv[j] - m2);                         s2 += e2[j];
        e1[j] = (qv[j] != 0.f) ? __expf(xv[j] - m1) : 0.f;  s1 += e1[j];
    }
    #pragma unroll
    for (int o = 16; o; o >>= 1) {
        s1 += __shfl_xor_sync(0xffffffffu, s1, o);
        s2 += __shfl_xor_sync(0xffffffffu, s2, o);
    }
    __syncthreads();
    if (lane == 0) { sh1[w] = s1; sh2[w] = s2; }
    __syncthreads();
    s1 = sh1[0] + sh1[1] + sh1[2] + sh1[3];
    s2 = sh2[0] + sh2[1] + sh2[2] + sh2[3];

    float r1 = 1.f / s1;
    float cm = Cmask[row];
    float r2 = (cm != 0.f) ? (1.f / s2) : __int_as_float(0x7FC00000);

    long o8 = (long)row * (M_ / 4) + t;   // uint2 index (4 fp16 per thread)
    {
        __half2 h0 = __floats2half2_rn(e1[0] * r1, e1[1] * r1);
        __half2 h1 = __floats2half2_rn(e1[2] * r1, e1[3] * r1);
        ((uint2*)g_S1)[o8] = make_uint2(h2u(h0), h2u(h1));
    }
    ((float4*)(g_S2 + (long)row * M_))[t] =
        make_float4(e2[0] * r2, e2[1] * r2, e2[2] * r2, e2[3] * r2);
}

// ===========================================================================
// 3-term bf16 GEMM (G1 only): D = (Ah+Al)·(Bh+Bl)^T, similarity epilogue.
// ===========================================================================
#define STAGE_ELEMS 20480
#define SMEM_BYTES  (2 * STAGE_ELEMS * 2)   // 81920

__device__ __forceinline__ void stage_load(__nv_bfloat16* sm, int buf,
    const __nv_bfloat16* __restrict__ Ahp, const __nv_bfloat16* __restrict__ Alp,
    const __nv_bfloat16* __restrict__ Bhp, const __nv_bfloat16* __restrict__ Blp,
    int lda, int ldb, int k0, int tid)
{
    #pragma unroll
    for (int it = 0; it < 2; ++it) {
        int v = tid + (it << 8);
        int r = v >> 2, j = v & 3;
        long aoff = (long)r * lda + k0 + j * 8;
        long boff = (long)r * ldb + k0 + j * 8;
        int  doff = buf * STAGE_ELEMS + r * 40 + j * 8;
        cp16(sm + doff,          Ahp + aoff);
        cp16(sm + doff + 5120,   Alp + aoff);
        cp16(sm + doff + 10240,  Bhp + boff);
        cp16(sm + doff + 15360,  Blp + boff);
    }
    CP_COMMIT();
}

__global__ __launch_bounds__(256)
void mma_gemm_sim(const __nv_bfloat16* __restrict__ Ah_, const __nv_bfloat16* __restrict__ Al_,
                  long sAb, int lda,
                  const __nv_bfloat16* __restrict__ Bh_, const __nv_bfloat16* __restrict__ Bl_,
                  long sBb, int ldb, int K,
                  float* __restrict__ simO,
                  const float* __restrict__ cw, const float* __restrict__ qw,
                  const float* __restrict__ biasp)
{
    extern __shared__ __nv_bfloat16 sm[];
    const int tid  = threadIdx.x;
    const int w    = tid >> 5, lane = tid & 31;
    const int g    = lane >> 2, t = lane & 3;
    const int wm   = w & 1, wn = w >> 1;
    const int b    = blockIdx.z;
    const int rowBase = blockIdx.y * 128;
    const int colBase = blockIdx.x * 128;

    const __nv_bfloat16* Ahp = Ah_ + (long)b * sAb + (long)rowBase * lda;
    const __nv_bfloat16* Alp = Al_ + (long)b * sAb + (long)rowBase * lda;
    const __nv_bfloat16* Bhp = Bh_ + (long)b * sBb + (long)colBase * ldb;
    const __nv_bfloat16* Blp = Bl_ + (long)b * sBb + (long)colBase * ldb;

    float d[4][4][4];
    #pragma unroll
    for (int mi = 0; mi < 4; ++mi)
        #pragma unroll
        for (int ni = 0; ni < 4; ++ni)
            #pragma unroll
            for (int r = 0; r < 4; ++r) d[mi][ni][r] = 0.f;

    const int NCH = K >> 5;
    stage_load(sm, 0, Ahp, Alp, Bhp, Blp, lda, ldb, 0, tid);

    for (int c = 0; c < NCH; ++c) {
        if (c + 1 < NCH) {
            stage_load(sm, (c + 1) & 1, Ahp, Alp, Bhp, Blp, lda, ldb, (c + 1) << 5, tid);
            CP_WAIT1();
        } else {
            CP_WAIT0();
        }
        __syncthreads();
        const __nv_bfloat16* S = sm + (c & 1) * STAGE_ELEMS;
        #pragma unroll
        for (int ks = 0; ks < 32; ks += 16) {
            unsigned ah[4][4], al[4][4], bh[4][2], bl[4][2];
            #pragma unroll
            for (int mi = 0; mi < 4; ++mi) {
                int i0 = (wm * 64 + mi * 16 + g) * 40 + ks + t * 2;
                ah[mi][0] = *(const unsigned*)(S + i0);
                ah[mi][1] = *(const unsigned*)(S + i0 + 320);
                ah[mi][2] = *(const unsigned*)(S + i0 + 8);
                ah[mi][3] = *(const unsigned*)(S + i0 + 328);
                al[mi][0] = *(const unsigned*)(S + i0 + 5120);
                al[mi][1] = *(const unsigned*)(S + i0 + 5440);
                al[mi][2] = *(const unsigned*)(S + i0 + 5128);
                al[mi][3] = *(const unsigned*)(S + i0 + 5448);
            }
            #pragma unroll
            for (int ni = 0; ni < 4; ++ni) {
                int i0 = 10240 + (wn * 32 + ni * 8 + g) * 40 + ks + t * 2;
                bh[ni][0] = *(const unsigned*)(S + i0);
                bh[ni][1] = *(const unsigned*)(S + i0 + 8);
                bl[ni][0] = *(const unsigned*)(S + i0 + 5120);
                bl[ni][1] = *(const unsigned*)(S + i0 + 5128);
            }
            #pragma unroll
            for (int mi = 0; mi < 4; ++mi)
                #pragma unroll
                for (int ni = 0; ni < 4; ++ni) {
                    mma_bf16(d[mi][ni], ah[mi], bh[ni]);
                    mma_bf16(d[mi][ni], ah[mi], bl[ni]);
                    mma_bf16(d[mi][ni], al[mi], bh[ni]);
                }
        }
        __syncthreads();
    }

    const int mrow0 = rowBase + wm * 64;
    const int ncol0 = colBase + wn * 32;
    float bb = biasp[0];
    #pragma unroll
    for (int mi = 0; mi < 4; ++mi) {
        int r0 = mrow0 + mi * 16 + g, r1 = r0 + 8;
        float c0 = cw[b * N_ + r0] + bb;
        float c1 = cw[b * N_ + r1] + bb;
        #pragma unroll
        for (int ni = 0; ni < 4; ++ni) {
            int col = ncol0 + ni * 8 + t * 2;
            float2 q = *(const float2*)(qw + b * M_ + col);
            *(float2*)(simO + ((long)b * N_ + r0) * M_ + col) =
                make_float2(d[mi][ni][0] + c0 + q.x, d[mi][ni][1] + c0 + q.y);
            *(float2*)(simO + ((long)b * N_ + r1) * M_ + col) =
                make_float2(d[mi][ni][2] + c1 + q.x, d[mi][ni][3] + c1 + q.y);
        }
    }
}

// ===========================================================================
// 1-term fp16 GEMM: D = A·Bg^T  (both single fp16; 1 MMA per pair).
// EPI: 2 = A-epilogue (dst[.,0:512]=C, [512:1024]=acc, [1024:1536]=C*acc)
//      3 = Bv-epilogue (dst[.,1536:2048]=C*acc)
//      4 = plain fp32 store -> dst, row stride D_, rows in [0,M)
// ===========================================================================
#define STAGE1_ELEMS 10240
#define SMEM1_BYTES  (2 * STAGE1_ELEMS * 2)   // 40960

__device__ __forceinline__ void stage_load1(__half* sm, int buf,
    const __half* __restrict__ Ap, const __half* __restrict__ Bp,
    int lda, int ldb, int k0, int tid)
{
    #pragma unroll
    for (int it = 0; it < 2; ++it) {
        int v = tid + (it << 8);
        int r = v >> 2, j = v & 3;
        int doff = buf * STAGE1_ELEMS + r * 40 + j * 8;
        cp16(sm + doff,        Ap + (long)r * lda + k0 + j * 8);
        cp16(sm + doff + 5120, Bp + (long)r * ldb + k0 + j * 8);
    }
    CP_COMMIT();
}

template<int EPI>
__global__ __launch_bounds__(256)
void mma_gemm1(const __half* __restrict__ Ag, long sAb, int lda,
               const __half* __restrict__ Bg, long sBb, int ldb, int K,
               const float* __restrict__ Cin, float* __restrict__ dst)
{
    extern __shared__ __half smh[];
    const int tid  = threadIdx.x;
    const int w    = tid >> 5, lane = tid & 31;
    const int g    = lane >> 2, t = lane & 3;
    const int wm   = w & 1, wn = w >> 1;
    const int b    = blockIdx.z;
    const int rowBase = blockIdx.y * 128;
    const int colBase = blockIdx.x * 128;

    const __half* Ap = Ag + (long)b * sAb + (long)rowBase * lda;
    const __half* Bp = Bg + (long)b * sBb + (long)colBase * ldb;

    float d[4][4][4];
    #pragma unroll
    for (int mi = 0; mi < 4; ++mi)
        #pragma unroll
        for (int ni = 0; ni < 4; ++ni)
            #pragma unroll
            for (int r = 0; r < 4; ++r) d[mi][ni][r] = 0.f;

    const int NCH = K >> 5;
    stage_load1(smh, 0, Ap, Bp, lda, ldb, 0, tid);

    for (int c = 0; c < NCH; ++c) {
        if (c + 1 < NCH) {
            stage_load1(smh, (c + 1) & 1, Ap, Bp, lda, ldb, (c + 1) << 5, tid);
            CP_WAIT1();
        } else {
            CP_WAIT0();
        }
        __syncthreads();
        const __half* S = smh + (c & 1) * STAGE1_ELEMS;
        #pragma unroll
        for (int ks = 0; ks < 32; ks += 16) {
            unsigned ah[4][4], bh[4][2];
            #pragma unroll
            for (int mi = 0; mi < 4; ++mi) {
                int i0 = (wm * 64 + mi * 16 + g) * 40 + ks + t * 2;
                ah[mi][0] = *(const unsigned*)(S + i0);
                ah[mi][1] = *(const unsigned*)(S + i0 + 320);
                ah[mi][2] = *(const unsigned*)(S + i0 + 8);
                ah[mi][3] = *(const unsigned*)(S + i0 + 328);
            }
            #pragma unroll
            for (int ni = 0; ni < 4; ++ni) {
                int i0 = 5120 + (wn * 32 + ni * 8 + g) * 40 + ks + t * 2;
                bh[ni][0] = *(const unsigned*)(S + i0);
                bh[ni][1] = *(const unsigned*)(S + i0 + 8);
            }
            #pragma unroll
            for (int mi = 0; mi < 4; ++mi)
                #pragma unroll
                for (int ni = 0; ni < 4; ++ni)
                    mma_f16(d[mi][ni], ah[mi], bh[ni]);
        }
        __syncthreads();
    }

    const int mrow0 = rowBase + wm * 64;
    const int ncol0 = colBase + wn * 32;

    if (EPI == 4) {
        #pragma unroll
        for (int mi = 0; mi < 4; ++mi) {
            int r0 = mrow0 + mi * 16 + g, r1 = r0 + 8;
            #pragma unroll
            for (int ni = 0; ni < 4; ++ni) {
                int col = ncol0 + ni * 8 + t * 2;
                *(float2*)(dst + ((long)b * M_ + r0) * D_ + col) =
                    make_float2(d[mi][ni][0], d[mi][ni][1]);
                *(float2*)(dst + ((long)b * M_ + r1) * D_ + col) =
                    make_float2(d[mi][ni][2], d[mi][ni][3]);
            }
        }
    } else {
        const float* Cb = Cin + (long)b * N_ * D_;
        float* Ob = dst + (long)b * N_ * 2048;
        #pragma unroll
        for (int mi = 0; mi < 4; ++mi) {
            int r0 = mrow0 + mi * 16 + g, r1 = r0 + 8;
            #pragma unroll
            for (int ni = 0; ni < 4; ++ni) {
                int col = ncol0 + ni * 8 + t * 2;
                float2 cv0 = *(const float2*)(Cb + (long)r0 * D_ + col);
                float2 cv1 = *(const float2*)(Cb + (long)r1 * D_ + col);
                float2 a0 = make_float2(d[mi][ni][0], d[mi][ni][1]);
                float2 a1 = make_float2(d[mi][ni][2], d[mi][ni][3]);
                float* o0 = Ob + (long)r0 * 2048;
                float* o1 = Ob + (long)r1 * 2048;
                if (EPI == 2) {
                    *(float2*)(o0 + col)        = cv0;
                    *(float2*)(o0 + 512 + col)  = a0;
                    *(float2*)(o0 + 1024 + col) = make_float2(cv0.x * a0.x, cv0.y * a0.y);
                    *(float2*)(o1 + col)        = cv1;
                    *(float2*)(o1 + 512 + col)  = a1;
                    *(float2*)(o1 + 1024 + col) = make_float2(cv1.x * a1.x, cv1.y * a1.y);
                } else { // EPI == 3
                    *(float2*)(o0 + 1536 + col) = make_float2(cv0.x * a0.x, cv0.y * a0.y);
                    *(float2*)(o1 + 1536 + col) = make_float2(cv1.x * a1.x, cv1.y * a1.y);
                }
            }
        }
    }
}

// ---------------------------------------------------------------------------
// kernel_launch
// inputs: C[B,N,D], Q[B,M,D], Cmask[B,N], Qmask[B,M], w4C[D], w4Q[D],
//         w4mlu[D], bias[1]; out: [B,N,4D] fp32
// ---------------------------------------------------------------------------
extern "C" void kernel_launch(void* const* d_in, const int* in_sizes, int n_in,
                              void* d_out, int out_size)
{
    (void)in_sizes; (void)n_in; (void)out_size;
    const float* C     = (const float*)d_in[0];
    const float* Q     = (const float*)d_in[1];
    const float* Cmask = (const float*)d_in[2];
    const float* Qmask = (const float*)d_in[3];
    const float* w4C   = (const float*)d_in[4];
    const float* w4Q   = (const float*)d_in[5];
    const float* w4mlu = (const float*)d_in[6];
    const float* bias  = (const float*)d_in[7];
    float* out = (float*)d_out;

    float *sim, *S2f, *Xf, *cw, *qw;
    __nv_bfloat16 *CWh, *CWl, *Qbh, *Qbl;
    __half *S1, *Qt, *Ct, *S2t, *Xt;
    cudaGetSymbolAddress((void**)&sim,  g_sim);
    cudaGetSymbolAddress((void**)&S2f,  g_S2);
    cudaGetSymbolAddress((void**)&Xf,   g_X);
    cudaGetSymbolAddress((void**)&cw,   g_cw);
    cudaGetSymbolAddress((void**)&qw,   g_qw);
    cudaGetSymbolAddress((void**)&CWh,  g_CWh);
    cudaGetSymbolAddress((void**)&CWl,  g_CWl);
    cudaGetSymbolAddress((void**)&Qbh,  g_Qbh);
    cudaGetSymbolAddress((void**)&Qbl,  g_Qbl);
    cudaGetSymbolAddress((void**)&S1,   g_S1);
    cudaGetSymbolAddress((void**)&Qt,   g_Qt);
    cudaGetSymbolAddress((void**)&Ct,   g_Ct);
    cudaGetSymbolAddress((void**)&S2t,  g_S2t);
    cudaGetSymbolAddress((void**)&Xt,   g_Xt);

    cudaFuncSetAttribute(mma_gemm_sim, cudaFuncAttributeMaxDynamicSharedMemorySize, SMEM_BYTES);
    cudaFuncSetAttribute(mma_gemm1<2>, cudaFuncAttributeMaxDynamicSharedMemorySize, SMEM1_BYTES);
    cudaFuncSetAttribute(mma_gemm1<3>, cudaFuncAttributeMaxDynamicSharedMemorySize, SMEM1_BYTES);
    cudaFuncSetAttribute(mma_gemm1<4>, cudaFuncAttributeMaxDynamicSharedMemorySize, SMEM1_BYTES);

    // 1) row scalars
    rowdot_kernel<<<(B_ * N_) / 8, 256>>>(C, w4C, cw, B_ * N_);
    rowdot_kernel<<<(B_ * M_) / 8, 256>>>(Q, w4Q, qw, B_ * M_);

    // 2) bf16 splits for G1: CW = (C*w4mlu), Q
    {
        int n4 = B_ * N_ * D_ / 4;
        split_kernel<true><<<n4 / 256, 256>>>(C, w4mlu, CWh, CWl, n4);
    }
    {
        int n4 = B_ * M_ * D_ / 4;
        split_kernel<false><<<n4 / 256, 256>>>(Q, nullptr, Qbh, Qbl, n4);
    }

    // 3) fp16 transposes: Qt [D,M], Ct [D,N]
    {
        dim3 g(D_ / 32, M_ / 32, B_);
        transpose_half_kernel<<<g, 256>>>(Q, M_, D_, Qt);
    }
    {
        dim3 g(D_ / 32, N_ / 32, B_);
        transpose_half_kernel<<<g, 256>>>(C, N_, D_, Ct);
    }

    // 4) G1 (3-term bf16): sim[n,m] = sum_d CW[n,d]*Q[m,d] + cw + qw + bias
    {
        dim3 g(M_ / 128, N_ / 128, B_);
        mma_gemm_sim<<<g, 256, SMEM_BYTES>>>(
            CWh, CWl, (long)N_ * D_, D_,
            Qbh, Qbl, (long)M_ * D_, D_,
            D_, sim, cw, qw, bias);
    }

    // 5) dual softmax -> S1 fp16, S2 fp32
    softmax2_kernel<<<B_ * N_, 128>>>(Qmask, Cmask);

    // 6) G2 (1-term fp16): A = S1 @ Q  -> out[:,0:1536] epilogue
    {
        dim3 g(D_ / 128, N_ / 128, B_);
        mma_gemm1<2><<<g, 256, SMEM1_BYTES>>>(
            S1, (long)N_ * M_, M_,
            Qt, (long)D_ * M_, M_,
            M_, C, out);
    }

    // 7) transpose S2 [N,M] -> S2t fp16 [M,N]
    {
        dim3 g(M_ / 32, N_ / 32, B_);
        transpose_half_kernel<<<g, 256>>>(S2f, N_, M_, S2t);
    }

    // 8) GX (1-term fp16): X[m,d] = sum_n S2t[m,n] * Ct[d,n] -> fp32 g_X [M,D]
    {
        dim3 g(D_ / 128, M_ / 128, B_);
        mma_gemm1<4><<<g, 256, SMEM1_BYTES>>>(
            S2t, (long)M_ * N_, N_,
            Ct,  (long)D_ * N_, N_,
            N_, nullptr, Xf);
    }

    // 9) transpose X [M,D] -> Xt fp16 [D,M]
    {
        dim3 g(D_ / 32, M_ / 32, B_);
        transpose_half_kernel<<<g, 256>>>(Xf, M_, D_, Xt);
    }

    // 10) G4 (1-term fp16): Bv = S1 @ X -> out[:,1536:2048] = C*Bv
    {
        dim3 g(D_ / 128, N_ / 128, B_);
        mma_gemm1<3><<<g, 256, SMEM1_BYTES>>>(
            S1, (long)N_ * M_, M_,
            Xt, (long)D_ * M_, M_,
            M_, C, out);
    }
}